// round 15
// baseline (speedup 1.0000x reference)
#include <cuda_runtime.h>
#include <cuda_fp16.h>
#include <cstdint>

// Problem constants
#define Nn   100000
#define Ee   1600000
#define HID  128
#define NG   512
#define NB_SCAN 98        // ceil(100000/1024)
#define NH_BLK 384        // row-block split point for agg0/gemm1 overlap
#define NH    (NH_BLK * 128)   // 49152

// ---------------- scratch (static device memory) -----------------------------
__device__ __align__(128) __half g_Hi[(size_t)Nn * 128];    // conv0 GEMM out
__device__ __align__(128) __half g_Hr[(size_t)Nn * 128];
__device__ __align__(128) __half g_Hi1[(size_t)Nn * 128];   // conv1 GEMM out (separate: no WAR with agg0)
__device__ __align__(128) __half g_Hr1[(size_t)Nn * 128];
__device__ __align__(128) __half g_A0[(size_t)Nn * 256];
__device__ __align__(128) __half g_A1[(size_t)Nn * 128];
__device__ __align__(128) __half g_B0[256 * 256];
__device__ __align__(128) __half g_B1[256 * 128];
__device__ float g_deg[Nn];
__device__ int   g_cnt[Nn];
__device__ int   g_off[Nn];
__device__ int   g_cur[Nn];
__device__ int   g_src[Ee];
__device__ float g_nrm_s[Ee];
__device__ int   g_psum[NB_SCAN];
__device__ int   g_boff[NB_SCAN];
__device__ float g_pool[NG * HID];
__device__ float g_pcnt[NG];

// ---------------- PTX helpers (base sm_100 features only) --------------------
__device__ __forceinline__ uint32_t s2u(const void* p) {
    uint32_t a;
    asm("{ .reg .u64 t; cvta.to.shared.u64 t, %1; cvt.u32.u64 %0, t; }" : "=r"(a) : "l"(p));
    return a;
}
__device__ __forceinline__ void ldm_x4(uint32_t& r0, uint32_t& r1, uint32_t& r2, uint32_t& r3,
                                       uint32_t addr) {
    asm volatile("ldmatrix.sync.aligned.m8n8.x4.shared.b16 {%0,%1,%2,%3}, [%4];"
                 : "=r"(r0), "=r"(r1), "=r"(r2), "=r"(r3) : "r"(addr));
}
__device__ __forceinline__ void ldm_x2(uint32_t& r0, uint32_t& r1, uint32_t addr) {
    asm volatile("ldmatrix.sync.aligned.m8n8.x2.shared.b16 {%0,%1}, [%2];"
                 : "=r"(r0), "=r"(r1) : "r"(addr));
}
__device__ __forceinline__ void mma_f16(float* c, const uint32_t* a, const uint32_t* b) {
    asm volatile(
        "mma.sync.aligned.m16n8k16.row.col.f32.f16.f16.f32 "
        "{%0,%1,%2,%3}, {%4,%5,%6,%7}, {%8,%9}, {%0,%1,%2,%3};"
        : "+f"(c[0]), "+f"(c[1]), "+f"(c[2]), "+f"(c[3])
        : "r"(a[0]), "r"(a[1]), "r"(a[2]), "r"(a[3]), "r"(b[0]), "r"(b[1]));
}
__device__ __forceinline__ void cpa16(uint32_t saddr, const void* gaddr) {
    asm volatile("cp.async.cg.shared.global [%0], [%1], 16;" :: "r"(saddr), "l"(gaddr));
}
__device__ __forceinline__ void cpa_commit(void) {
    asm volatile("cp.async.commit_group;" ::: "memory");
}
template <int N>
__device__ __forceinline__ void cpa_wait(void) {
    asm volatile("cp.async.wait_group %0;" :: "n"(N) : "memory");
}

// ---------------- fused zero + CSR build kernels ------------------------------
__global__ void k_zero(void) {
    int i = blockIdx.x * blockDim.x + threadIdx.x;
    if (i < Nn) { g_deg[i] = 0.f; g_cnt[i] = 0; }
    if (i < NG * HID) g_pool[i] = 0.f;
    if (i < NG) g_pcnt[i] = 0.f;
}
__global__ void k_degcnt(const int* __restrict__ ei, const float* __restrict__ w) {
    int e = blockIdx.x * blockDim.x + threadIdx.x;
    if (e >= Ee) return;
    int col = ei[Ee + e];
    atomicAdd(&g_deg[col], w[e]);
    atomicAdd(&g_cnt[col], 1);
}
__global__ void k_scan1(void) {
    __shared__ int s[1024];
    int t = threadIdx.x;
    int i = blockIdx.x * 1024 + t;
    if (i < Nn) {
        float d = g_deg[i];
        g_deg[i] = (d > 0.f) ? rsqrtf(d) : 0.f;
    }
    s[t] = (i < Nn) ? g_cnt[i] : 0;
    __syncthreads();
    for (int d = 512; d > 0; d >>= 1) {
        if (t < d) s[t] += s[t + d];
        __syncthreads();
    }
    if (t == 0) g_psum[blockIdx.x] = s[0];
}
__global__ void k_scan2(void) {
    __shared__ int warpsum[4];
    int t = threadIdx.x;
    int lane = t & 31, w = t >> 5;
    int v = (t < NB_SCAN) ? g_psum[t] : 0;
    int inc = v;
    #pragma unroll
    for (int d = 1; d < 32; d <<= 1) {
        int o = __shfl_up_sync(0xFFFFFFFF, inc, d);
        if (lane >= d) inc += o;
    }
    if (lane == 31) warpsum[w] = inc;
    __syncthreads();
    int base = 0;
    #pragma unroll
    for (int k = 0; k < 4; k++) if (k < w) base += warpsum[k];
    if (t < NB_SCAN) g_boff[t] = base + inc - v;
}
__global__ void k_scan3(void) {
    __shared__ int s[1024];
    int t = threadIdx.x;
    int i = blockIdx.x * 1024 + t;
    int v = (i < Nn) ? g_cnt[i] : 0;
    s[t] = v;
    __syncthreads();
    for (int d = 1; d < 1024; d <<= 1) {
        int add = (t >= d) ? s[t - d] : 0;
        __syncthreads();
        s[t] += add;
        __syncthreads();
    }
    if (i < Nn) {
        int excl = g_boff[blockIdx.x] + s[t] - v;
        g_off[i] = excl;
        g_cur[i] = excl;
    }
}
__global__ void k_scatter(const int* __restrict__ ei, const float* __restrict__ w) {
    int e = blockIdx.x * blockDim.x + threadIdx.x;
    if (e >= Ee) return;
    int row = ei[e];
    int col = ei[Ee + e];
    int pos = atomicAdd(&g_cur[col], 1);
    g_src[pos] = row;
    g_nrm_s[pos] = g_deg[row] * w[e] * g_deg[col];
}

// ---------------- fp16 conversion preps --------------------------------------
__global__ void k_split_x(const float* __restrict__ x) {
    size_t i = (size_t)blockIdx.x * blockDim.x + threadIdx.x;
    if (i >= (size_t)Nn * 64) return;
    float4 v = ((const float4*)x)[i];
    __half2 a = __halves2half2(__float2half(v.x), __float2half(v.y));
    __half2 b = __halves2half2(__float2half(v.z), __float2half(v.w));
    ((__half2*)g_A0)[i * 2 + 0] = a;
    ((__half2*)g_A0)[i * 2 + 1] = b;
}
template <bool FIRST>
__global__ void k_wsplit(const float* __restrict__ wi, const float* __restrict__ wr) {
    const int K = FIRST ? 256 : 128;
    int idx = blockIdx.x * blockDim.x + threadIdx.x;
    if (idx >= 256 * K) return;
    int n = idx / K, k = idx % K;
    float w = (n < 128) ? wi[k * 128 + n] : wr[k * 128 + (n - 128)];
    if (FIRST) g_B0[idx] = __float2half(w);
    else       g_B1[idx] = __float2half(w);
}

// ---------------- pipelined mma.sync GEMM (BK=64, dynamic smem) --------------
#define SROW 72
#define TILE_HALVES (128 * SROW)
#define SMEM_BYTES (4 * TILE_HALVES * 2)
template <bool FIRST>
__global__ void __launch_bounds__(256, 2) k_mma(int rowOfs) {
    constexpr int K  = FIRST ? 256 : 128;
    constexpr int NC = K / 64;
    extern __shared__ __align__(16) __half smem[];
    __half* sA[2] = { smem,                   smem + 2 * TILE_HALVES };
    __half* sB[2] = { smem + TILE_HALVES,     smem + 3 * TILE_HALVES };

    const __half* Aw = FIRST ? g_A0 : g_A1;
    const __half* Bw = FIRST ? g_B0 : g_B1;

    int tid = threadIdx.x, lane = tid & 31, wid = tid >> 5;
    int warp_m = wid >> 2;
    int warp_n = wid & 3;
    int rowBase = (rowOfs + blockIdx.x) * 128;
    __half* Hout;
    if (FIRST) Hout = (blockIdx.y == 0) ? g_Hi : g_Hr;
    else       Hout = (blockIdx.y == 0) ? g_Hi1 : g_Hr1;
    int nBase = blockIdx.y * 128;

    auto issue_chunk = [&](int c, int buf) {
        int k0 = c * 64;
        #pragma unroll
        for (int j = tid; j < 2048; j += 256) {
            int isB = j >= 1024;
            int i = j & 1023;
            int row = i >> 3, q = i & 7;
            const __half* src;
            if (!isB) {
                int rg = rowBase + row;
                if (rg >= Nn) rg = Nn - 1;
                src = &Aw[(size_t)rg * K + k0 + q * 8];
            } else {
                src = &Bw[(size_t)(nBase + row) * K + k0 + q * 8];
            }
            uint32_t dst = s2u(&(isB ? sB : sA)[buf][row * SROW + q * 8]);
            cpa16(dst, src);
        }
        cpa_commit();
    };

    float acc[4][4][4] = {};

    issue_chunk(0, 0);
    for (int c = 0; c < NC; ++c) {
        int buf = c & 1;
        cpa_wait<0>();
        __syncthreads();
        if (c + 1 < NC) issue_chunk(c + 1, buf ^ 1);
        uint32_t aB = s2u(sA[buf]), bB = s2u(sB[buf]);
        #pragma unroll
        for (int kk = 0; kk < 4; kk++) {
            int k16 = kk * 16;
            uint32_t a[4][4];
            #pragma unroll
            for (int mt = 0; mt < 4; mt++) {
                int row = warp_m * 64 + mt * 16 + (lane & 15);
                uint32_t addr = aB + (uint32_t)(row * SROW + k16 + (lane >> 4) * 8) * 2;
                ldm_x4(a[mt][0], a[mt][1], a[mt][2], a[mt][3], addr);
            }
            uint32_t b[4][2];
            #pragma unroll
            for (int nt = 0; nt < 4; nt++) {
                int row = warp_n * 32 + nt * 8 + (lane & 7);
                uint32_t addr = bB + (uint32_t)(row * SROW + k16 + ((lane >> 3) & 1) * 8) * 2;
                ldm_x2(b[nt][0], b[nt][1], addr);
            }
            #pragma unroll
            for (int mt = 0; mt < 4; mt++)
                #pragma unroll
                for (int nt = 0; nt < 4; nt++)
                    mma_f16(acc[mt][nt], a[mt], b[nt]);
        }
        __syncthreads();
    }

    #pragma unroll
    for (int mt = 0; mt < 4; mt++) {
        int m0 = rowBase + warp_m * 64 + mt * 16 + (lane >> 2);
        int m1 = m0 + 8;
        #pragma unroll
        for (int nt = 0; nt < 4; nt++) {
            int col = warp_n * 32 + nt * 8 + (lane & 3) * 2;
            if (m0 < Nn) {
                *(__half2*)&Hout[(size_t)m0 * 128 + col] =
                    __halves2half2(__float2half(acc[mt][nt][0]), __float2half(acc[mt][nt][1]));
            }
            if (m1 < Nn) {
                *(__half2*)&Hout[(size_t)m1 * 128 + col] =
                    __halves2half2(__float2half(acc[mt][nt][2]), __float2half(acc[mt][nt][3]));
            }
        }
    }
}

// ---------------- Aggregation: warp per node, fp16 gathers -------------------
__device__ __forceinline__ void gather_add(float4& acc, const __half* rowp, float nm) {
    uint2 u = *(const uint2*)rowp;
    float2 f0 = __half22float2(*(__half2*)&u.x);
    float2 f1 = __half22float2(*(__half2*)&u.y);
    acc.x += nm * f0.x; acc.y += nm * f0.y;
    acc.z += nm * f1.x; acc.w += nm * f1.y;
}

// agg0 reads g_Hi/g_Hr (conv0 buffers) ONLY — conv1 GEMM writes g_Hi1/g_Hr1,
// so the concurrent gemm1_a / agg0_b overlap has no aliasing.
__global__ void k_agg0(const float* __restrict__ bias, int nodeOfs, int nodeEnd) {
    int warp = threadIdx.x >> 5;
    int lane = threadIdx.x & 31;
    int n = nodeOfs + blockIdx.x * 8 + warp;
    if (n >= nodeEnd) return;
    int e = g_off[n];
    int end = e + g_cnt[n];
    float4 acc = make_float4(0.f, 0.f, 0.f, 0.f);
    for (; e + 1 < end; e += 2) {
        int s0 = g_src[e], s1 = g_src[e + 1];
        float n0 = g_nrm_s[e], n1 = g_nrm_s[e + 1];
        gather_add(acc, &g_Hi[(size_t)s0 * 128 + lane * 4], n0);
        gather_add(acc, &g_Hi[(size_t)s1 * 128 + lane * 4], n1);
    }
    if (e < end) {
        gather_add(acc, &g_Hi[(size_t)g_src[e] * 128 + lane * 4], g_nrm_s[e]);
    }
    float4 r;
    {
        uint2 u = *(const uint2*)&g_Hr[(size_t)n * 128 + lane * 4];
        float2 f0 = __half22float2(*(__half2*)&u.x);
        float2 f1 = __half22float2(*(__half2*)&u.y);
        r = make_float4(f0.x, f0.y, f1.x, f1.y);
    }
    float4 b = *(const float4*)&bias[lane * 4];
    float o0 = fmaxf(acc.x + r.x + b.x, 0.f);
    float o1 = fmaxf(acc.y + r.y + b.y, 0.f);
    float o2 = fmaxf(acc.z + r.z + b.z, 0.f);
    float o3 = fmaxf(acc.w + r.w + b.w, 0.f);
    __half2* ph = (__half2*)&g_A1[(size_t)n * 128 + lane * 4];
    ph[0] = __halves2half2(__float2half(o0), __float2half(o1));
    ph[1] = __halves2half2(__float2half(o2), __float2half(o3));
}

// agg1 reads conv1 buffers g_Hi1/g_Hr1
__global__ void k_agg1(const float* __restrict__ bias, const int* __restrict__ batch) {
    int warp = threadIdx.x >> 5;
    int lane = threadIdx.x & 31;
    int n = blockIdx.x * 8 + warp;
    if (n >= Nn) return;
    int e = g_off[n];
    int end = e + g_cnt[n];
    float4 acc = make_float4(0.f, 0.f, 0.f, 0.f);
    for (; e + 1 < end; e += 2) {
        int s0 = g_src[e], s1 = g_src[e + 1];
        float n0 = g_nrm_s[e], n1 = g_nrm_s[e + 1];
        gather_add(acc, &g_Hi1[(size_t)s0 * 128 + lane * 4], n0);
        gather_add(acc, &g_Hi1[(size_t)s1 * 128 + lane * 4], n1);
    }
    if (e < end) {
        gather_add(acc, &g_Hi1[(size_t)g_src[e] * 128 + lane * 4], g_nrm_s[e]);
    }
    float4 r;
    {
        uint2 u = *(const uint2*)&g_Hr1[(size_t)n * 128 + lane * 4];
        float2 f0 = __half22float2(*(__half2*)&u.x);
        float2 f1 = __half22float2(*(__half2*)&u.y);
        r = make_float4(f0.x, f0.y, f1.x, f1.y);
    }
    float4 b = *(const float4*)&bias[lane * 4];
    float4 o;
    o.x = fmaxf(acc.x + r.x + b.x, 0.f);
    o.y = fmaxf(acc.y + r.y + b.y, 0.f);
    o.z = fmaxf(acc.z + r.z + b.z, 0.f);
    o.w = fmaxf(acc.w + r.w + b.w, 0.f);
    int g = batch[n];
    float* p = &g_pool[(size_t)g * 128 + lane * 4];
    atomicAdd(p + 0, o.x);
    atomicAdd(p + 1, o.y);
    atomicAdd(p + 2, o.z);
    atomicAdd(p + 3, o.w);
    if (lane == 0) atomicAdd(&g_pcnt[g], 1.f);
}

// ---------------- pool finalize + MLP ----------------------------------------
__global__ void k_mlp(const float* __restrict__ w1, const float* __restrict__ b1,
                      const float* __restrict__ w2, const float* __restrict__ b2,
                      float* __restrict__ out) {
    __shared__ float gx[128];
    __shared__ float hid[256];
    int g = blockIdx.x;
    int t = threadIdx.x;
    if (t < 128) {
        float c = fmaxf(g_pcnt[g], 1.f);
        gx[t] = g_pool[(size_t)g * 128 + t] / c;
    }
    __syncthreads();
    float acc = b1[t];
    #pragma unroll 8
    for (int k = 0; k < 128; k++) acc += gx[k] * w1[k * 256 + t];
    hid[t] = fmaxf(acc, 0.f);
    __syncthreads();
    int warp = t >> 5, lane = t & 31;
    if (warp < 2) {
        int c = warp;
        float s = 0.f;
        for (int k = lane; k < 256; k += 32) s += hid[k] * w2[k * 2 + c];
        #pragma unroll
        for (int d = 16; d > 0; d >>= 1) s += __shfl_xor_sync(0xFFFFFFFF, s, d);
        if (lane == 0) out[g * 2 + c] = s + b2[c];
    }
}

// ---------------- launch -----------------------------------------------------
extern "C" void kernel_launch(void* const* d_in, const int* in_sizes, int n_in,
                              void* d_out, int out_size) {
    const float* x     = (const float*)d_in[0];
    const int*   ei    = (const int*)d_in[1];
    const float* ea    = (const float*)d_in[2];
    const int*   batch = (const int*)d_in[3];
    const float* w_init0 = (const float*)d_in[4];
    const float* w_root0 = (const float*)d_in[5];
    const float* b0      = (const float*)d_in[6];
    const float* w_init1 = (const float*)d_in[7];
    const float* w_root1 = (const float*)d_in[8];
    const float* b1      = (const float*)d_in[9];
    const float* mlp_w1  = (const float*)d_in[10];
    const float* mlp_b1  = (const float*)d_in[11];
    const float* mlp_w2  = (const float*)d_in[12];
    const float* mlp_b2  = (const float*)d_in[13];
    float* out = (float*)d_out;

    cudaFuncSetAttribute(k_mma<true>,  cudaFuncAttributeMaxDynamicSharedMemorySize, SMEM_BYTES);
    cudaFuncSetAttribute(k_mma<false>, cudaFuncAttributeMaxDynamicSharedMemorySize, SMEM_BYTES);

    const int TB = 256;
    int nBlkE = (Ee + TB - 1) / TB;
    int nz = ((NG * HID > Nn ? NG * HID : Nn) + TB - 1) / TB;
    dim3 gg0((Nn + 127) / 128, 2);

    cudaStream_t s2, s3;
    cudaEvent_t evFork, evJoin, evH, evG1a;
    bool forked = (cudaStreamCreateWithFlags(&s2, cudaStreamNonBlocking) == cudaSuccess) &&
                  (cudaStreamCreateWithFlags(&s3, cudaStreamNonBlocking) == cudaSuccess) &&
                  (cudaEventCreateWithFlags(&evFork, cudaEventDisableTiming) == cudaSuccess) &&
                  (cudaEventCreateWithFlags(&evJoin, cudaEventDisableTiming) == cudaSuccess) &&
                  (cudaEventCreateWithFlags(&evH, cudaEventDisableTiming) == cudaSuccess) &&
                  (cudaEventCreateWithFlags(&evG1a, cudaEventDisableTiming) == cudaSuccess);

    if (forked && cudaEventRecord(evFork, 0) == cudaSuccess &&
        cudaStreamWaitEvent(s2, evFork, 0) == cudaSuccess &&
        cudaStreamWaitEvent(s3, evFork, 0) == cudaSuccess) {
        // submission order chosen so ncu -s 5 captures k_mma<true> (launch #6)
        k_zero<<<nz, TB, 0, s2>>>();                                         // 1
        k_degcnt<<<nBlkE, TB, 0, s2>>>(ei, ea);                              // 2
        k_split_x<<<(Nn * 64 + TB - 1) / TB, TB>>>(x);                       // 3
        k_wsplit<true><<<(256 * 256 + TB - 1) / TB, TB>>>(w_init0, w_root0); // 4
        k_wsplit<false><<<(256 * 128 + TB - 1) / TB, TB>>>(w_init1, w_root1);// 5
        k_mma<true><<<gg0, 256, SMEM_BYTES>>>(0);                            // 6 <- profiled
        // rest of CSR chain on s2
        k_scan1<<<NB_SCAN, 1024, 0, s2>>>();
        k_scan2<<<1, 128, 0, s2>>>();
        k_scan3<<<NB_SCAN, 1024, 0, s2>>>();
        k_scatter<<<nBlkE, TB, 0, s2>>>(ei, ea);
        cudaEventRecord(evJoin, s2);

        cudaStreamWaitEvent(0, evJoin, 0);

        // agg0_a, then gemm1_a (s3, writes g_Hi1/g_Hr1) || agg0_b (0, reads g_Hi/g_Hr)
        k_agg0<<<(NH + 7) / 8, 256>>>(b0, 0, NH);
        cudaEventRecord(evH, 0);
        cudaStreamWaitEvent(s3, evH, 0);
        {
            dim3 g1a(NH_BLK, 2);
            k_mma<false><<<g1a, 256, SMEM_BYTES, s3>>>(0);
        }
        cudaEventRecord(evG1a, s3);
        k_agg0<<<(Nn - NH + 7) / 8, 256>>>(b0, NH, Nn);
        {
            dim3 g1b((Nn + 127) / 128 - NH_BLK, 2);
            k_mma<false><<<g1b, 256, SMEM_BYTES>>>(NH_BLK);
        }
        cudaStreamWaitEvent(0, evG1a, 0);

        k_agg1<<<(Nn + 7) / 8, 256>>>(b1, batch);
        k_mlp<<<NG, 256>>>(mlp_w1, mlp_b1, mlp_w2, mlp_b2, out);
    } else {
        // serial fallback
        k_zero<<<nz, TB>>>();
        k_degcnt<<<nBlkE, TB>>>(ei, ea);
        k_scan1<<<NB_SCAN, 1024>>>();
        k_scan2<<<1, 128>>>();
        k_scan3<<<NB_SCAN, 1024>>>();
        k_scatter<<<nBlkE, TB>>>(ei, ea);
        k_split_x<<<(Nn * 64 + TB - 1) / TB, TB>>>(x);
        k_wsplit<true><<<(256 * 256 + TB - 1) / TB, TB>>>(w_init0, w_root0);
        k_wsplit<false><<<(256 * 128 + TB - 1) / TB, TB>>>(w_init1, w_root1);
        k_mma<true><<<gg0, 256, SMEM_BYTES>>>(0);
        k_agg0<<<(Nn + 7) / 8, 256>>>(b0, 0, Nn);
        k_mma<false><<<gg0, 256, SMEM_BYTES>>>(0);
        k_agg1<<<(Nn + 7) / 8, 256>>>(b1, batch);
        k_mlp<<<NG, 256>>>(mlp_w1, mlp_b1, mlp_w2, mlp_b2, out);
    }

    if (forked) {
        cudaStreamDestroy(s2);
        cudaStreamDestroy(s3);
        cudaEventDestroy(evFork);
        cudaEventDestroy(evJoin);
        cudaEventDestroy(evH);
        cudaEventDestroy(evG1a);
    }
}

// round 16
// speedup vs baseline: 1.0160x; 1.0160x over previous
#include <cuda_runtime.h>
#include <cuda_fp16.h>
#include <cstdint>

// Problem constants
#define Nn   100000
#define Ee   1600000
#define HID  128
#define NG   512
#define NB_SCAN 98        // ceil(100000/1024)

// ---------------- scratch (static device memory) -----------------------------
__device__ __align__(128) __half g_Hi[(size_t)Nn * 128];
__device__ __align__(128) __half g_Hr[(size_t)Nn * 128];
__device__ __align__(128) __half g_A0[(size_t)Nn * 256];
__device__ __align__(128) __half g_A1[(size_t)Nn * 128];
__device__ __align__(128) __half g_B0[256 * 256];
__device__ __align__(128) __half g_B1[256 * 128];
__device__ float g_deg[Nn];
__device__ int   g_cnt[Nn];
__device__ int   g_off[Nn];
__device__ int   g_cur[Nn];
__device__ int   g_src[Ee];
__device__ float g_nrm_s[Ee];
__device__ int   g_psum[NB_SCAN];
__device__ float g_pool[NG * HID];
__device__ float g_pcnt[NG];

// ---------------- PTX helpers (base sm_100 features only) --------------------
__device__ __forceinline__ uint32_t s2u(const void* p) {
    uint32_t a;
    asm("{ .reg .u64 t; cvta.to.shared.u64 t, %1; cvt.u32.u64 %0, t; }" : "=r"(a) : "l"(p));
    return a;
}
__device__ __forceinline__ void ldm_x4(uint32_t& r0, uint32_t& r1, uint32_t& r2, uint32_t& r3,
                                       uint32_t addr) {
    asm volatile("ldmatrix.sync.aligned.m8n8.x4.shared.b16 {%0,%1,%2,%3}, [%4];"
                 : "=r"(r0), "=r"(r1), "=r"(r2), "=r"(r3) : "r"(addr));
}
__device__ __forceinline__ void ldm_x2(uint32_t& r0, uint32_t& r1, uint32_t addr) {
    asm volatile("ldmatrix.sync.aligned.m8n8.x2.shared.b16 {%0,%1}, [%2];"
                 : "=r"(r0), "=r"(r1) : "r"(addr));
}
__device__ __forceinline__ void mma_f16(float* c, const uint32_t* a, const uint32_t* b) {
    asm volatile(
        "mma.sync.aligned.m16n8k16.row.col.f32.f16.f16.f32 "
        "{%0,%1,%2,%3}, {%4,%5,%6,%7}, {%8,%9}, {%0,%1,%2,%3};"
        : "+f"(c[0]), "+f"(c[1]), "+f"(c[2]), "+f"(c[3])
        : "r"(a[0]), "r"(a[1]), "r"(a[2]), "r"(a[3]), "r"(b[0]), "r"(b[1]));
}
__device__ __forceinline__ void cpa16(uint32_t saddr, const void* gaddr) {
    asm volatile("cp.async.cg.shared.global [%0], [%1], 16;" :: "r"(saddr), "l"(gaddr));
}
__device__ __forceinline__ void cpa_commit(void) {
    asm volatile("cp.async.commit_group;" ::: "memory");
}
template <int N>
__device__ __forceinline__ void cpa_wait(void) {
    asm volatile("cp.async.wait_group %0;" :: "n"(N) : "memory");
}

// ---------------- fused zero + CSR build kernels ------------------------------
__global__ void k_zero(void) {
    int i = blockIdx.x * blockDim.x + threadIdx.x;
    if (i < Nn) { g_deg[i] = 0.f; g_cnt[i] = 0; }
    if (i < NG * HID) g_pool[i] = 0.f;
    if (i < NG) g_pcnt[i] = 0.f;
}
__global__ void k_degcnt(const int* __restrict__ ei, const float* __restrict__ w) {
    int e = blockIdx.x * blockDim.x + threadIdx.x;
    if (e >= Ee) return;
    int col = ei[Ee + e];
    atomicAdd(&g_deg[col], w[e]);
    atomicAdd(&g_cnt[col], 1);
}
// scan1: fused dinv + per-block sums
__global__ void k_scan1(void) {
    __shared__ int s[1024];
    int t = threadIdx.x;
    int i = blockIdx.x * 1024 + t;
    if (i < Nn) {
        float d = g_deg[i];
        g_deg[i] = (d > 0.f) ? rsqrtf(d) : 0.f;
    }
    s[t] = (i < Nn) ? g_cnt[i] : 0;
    __syncthreads();
    for (int d = 512; d > 0; d >>= 1) {
        if (t < d) s[t] += s[t + d];
        __syncthreads();
    }
    if (t == 0) g_psum[blockIdx.x] = s[0];
}
// scan3: fused block-base reduction (replaces scan2) + intra-block scan
__global__ void k_scan3(void) {
    __shared__ int s[1024];
    __shared__ int s_base;
    int t = threadIdx.x;
    int i = blockIdx.x * 1024 + t;
    // base = sum of g_psum[0..blockIdx.x)
    s[t] = (t < blockIdx.x && t < NB_SCAN) ? g_psum[t] : 0;
    __syncthreads();
    for (int d = 512; d > 0; d >>= 1) {
        if (t < d) s[t] += s[t + d];
        __syncthreads();
    }
    if (t == 0) s_base = s[0];
    __syncthreads();
    int base = s_base;
    // inclusive scan of this block's counts
    int v = (i < Nn) ? g_cnt[i] : 0;
    s[t] = v;
    __syncthreads();
    for (int d = 1; d < 1024; d <<= 1) {
        int add = (t >= d) ? s[t - d] : 0;
        __syncthreads();
        s[t] += add;
        __syncthreads();
    }
    if (i < Nn) {
        int excl = base + s[t] - v;
        g_off[i] = excl;
        g_cur[i] = excl;
    }
}
__global__ void k_scatter(const int* __restrict__ ei, const float* __restrict__ w) {
    int e = blockIdx.x * blockDim.x + threadIdx.x;
    if (e >= Ee) return;
    int row = ei[e];
    int col = ei[Ee + e];
    int pos = atomicAdd(&g_cur[col], 1);
    g_src[pos] = row;
    g_nrm_s[pos] = g_deg[row] * w[e] * g_deg[col];
}

// ---------------- fp16 conversion preps --------------------------------------
__global__ void k_split_x(const float* __restrict__ x) {
    size_t i = (size_t)blockIdx.x * blockDim.x + threadIdx.x;
    if (i >= (size_t)Nn * 64) return;
    float4 v = ((const float4*)x)[i];
    __half2 a = __halves2half2(__float2half(v.x), __float2half(v.y));
    __half2 b = __halves2half2(__float2half(v.z), __float2half(v.w));
    ((__half2*)g_A0)[i * 2 + 0] = a;
    ((__half2*)g_A0)[i * 2 + 1] = b;
}
// merged weight conversion: both conv weight sets in one launch
__global__ void k_wsplit(const float* __restrict__ wi0, const float* __restrict__ wr0,
                         const float* __restrict__ wi1, const float* __restrict__ wr1) {
    int idx = blockIdx.x * blockDim.x + threadIdx.x;
    if (idx < 256 * 256) {
        int n = idx >> 8, k = idx & 255;          // K=256
        float w = (n < 128) ? wi0[k * 128 + n] : wr0[k * 128 + (n - 128)];
        g_B0[idx] = __float2half(w);
    } else if (idx < 256 * 256 + 256 * 128) {
        int j = idx - 256 * 256;
        int n = j >> 7, k = j & 127;              // K=128
        float w = (n < 128) ? wi1[k * 128 + n] : wr1[k * 128 + (n - 128)];
        g_B1[j] = __float2half(w);
    }
}

// ---------------- pipelined mma.sync GEMM (BK=64, dynamic smem) --------------
#define SROW 72
#define TILE_HALVES (128 * SROW)
#define SMEM_BYTES (4 * TILE_HALVES * 2)
template <bool FIRST>
__global__ void __launch_bounds__(256, 2) k_mma(void) {
    constexpr int K  = FIRST ? 256 : 128;
    constexpr int NC = K / 64;
    extern __shared__ __align__(16) __half smem[];
    __half* sA[2] = { smem,                   smem + 2 * TILE_HALVES };
    __half* sB[2] = { smem + TILE_HALVES,     smem + 3 * TILE_HALVES };

    const __half* Aw = FIRST ? g_A0 : g_A1;
    const __half* Bw = FIRST ? g_B0 : g_B1;

    int tid = threadIdx.x, lane = tid & 31, wid = tid >> 5;
    int warp_m = wid >> 2;
    int warp_n = wid & 3;
    int rowBase = blockIdx.x * 128;
    __half* Hout = (blockIdx.y == 0) ? g_Hi : g_Hr;
    int nBase = blockIdx.y * 128;

    auto issue_chunk = [&](int c, int buf) {
        int k0 = c * 64;
        #pragma unroll
        for (int j = tid; j < 2048; j += 256) {
            int isB = j >= 1024;
            int i = j & 1023;
            int row = i >> 3, q = i & 7;
            const __half* src;
            if (!isB) {
                int rg = rowBase + row;
                if (rg >= Nn) rg = Nn - 1;
                src = &Aw[(size_t)rg * K + k0 + q * 8];
            } else {
                src = &Bw[(size_t)(nBase + row) * K + k0 + q * 8];
            }
            uint32_t dst = s2u(&(isB ? sB : sA)[buf][row * SROW + q * 8]);
            cpa16(dst, src);
        }
        cpa_commit();
    };

    float acc[4][4][4] = {};

    issue_chunk(0, 0);
    for (int c = 0; c < NC; ++c) {
        int buf = c & 1;
        cpa_wait<0>();
        __syncthreads();
        if (c + 1 < NC) issue_chunk(c + 1, buf ^ 1);
        uint32_t aB = s2u(sA[buf]), bB = s2u(sB[buf]);
        #pragma unroll
        for (int kk = 0; kk < 4; kk++) {
            int k16 = kk * 16;
            uint32_t a[4][4];
            #pragma unroll
            for (int mt = 0; mt < 4; mt++) {
                int row = warp_m * 64 + mt * 16 + (lane & 15);
                uint32_t addr = aB + (uint32_t)(row * SROW + k16 + (lane >> 4) * 8) * 2;
                ldm_x4(a[mt][0], a[mt][1], a[mt][2], a[mt][3], addr);
            }
            uint32_t b[4][2];
            #pragma unroll
            for (int nt = 0; nt < 4; nt++) {
                int row = warp_n * 32 + nt * 8 + (lane & 7);
                uint32_t addr = bB + (uint32_t)(row * SROW + k16 + ((lane >> 3) & 1) * 8) * 2;
                ldm_x2(b[nt][0], b[nt][1], addr);
            }
            #pragma unroll
            for (int mt = 0; mt < 4; mt++)
                #pragma unroll
                for (int nt = 0; nt < 4; nt++)
                    mma_f16(acc[mt][nt], a[mt], b[nt]);
        }
        __syncthreads();
    }

    #pragma unroll
    for (int mt = 0; mt < 4; mt++) {
        int m0 = rowBase + warp_m * 64 + mt * 16 + (lane >> 2);
        int m1 = m0 + 8;
        #pragma unroll
        for (int nt = 0; nt < 4; nt++) {
            int col = warp_n * 32 + nt * 8 + (lane & 3) * 2;
            if (m0 < Nn) {
                *(__half2*)&Hout[(size_t)m0 * 128 + col] =
                    __halves2half2(__float2half(acc[mt][nt][0]), __float2half(acc[mt][nt][1]));
            }
            if (m1 < Nn) {
                *(__half2*)&Hout[(size_t)m1 * 128 + col] =
                    __halves2half2(__float2half(acc[mt][nt][2]), __float2half(acc[mt][nt][3]));
            }
        }
    }
}

// ---------------- Aggregation: warp per node, fp16 gathers -------------------
__device__ __forceinline__ void gather_add(float4& acc, const __half* rowp, float nm) {
    uint2 u = *(const uint2*)rowp;
    float2 f0 = __half22float2(*(__half2*)&u.x);
    float2 f1 = __half22float2(*(__half2*)&u.y);
    acc.x += nm * f0.x; acc.y += nm * f0.y;
    acc.z += nm * f1.x; acc.w += nm * f1.y;
}

__global__ void k_agg0(const float* __restrict__ bias) {
    int warp = threadIdx.x >> 5;
    int lane = threadIdx.x & 31;
    int n = blockIdx.x * 8 + warp;
    if (n >= Nn) return;
    int e = g_off[n];
    int end = e + g_cnt[n];
    float4 acc = make_float4(0.f, 0.f, 0.f, 0.f);
    for (; e + 1 < end; e += 2) {
        int s0 = g_src[e], s1 = g_src[e + 1];
        float n0 = g_nrm_s[e], n1 = g_nrm_s[e + 1];
        gather_add(acc, &g_Hi[(size_t)s0 * 128 + lane * 4], n0);
        gather_add(acc, &g_Hi[(size_t)s1 * 128 + lane * 4], n1);
    }
    if (e < end) {
        gather_add(acc, &g_Hi[(size_t)g_src[e] * 128 + lane * 4], g_nrm_s[e]);
    }
    float4 r;
    {
        uint2 u = *(const uint2*)&g_Hr[(size_t)n * 128 + lane * 4];
        float2 f0 = __half22float2(*(__half2*)&u.x);
        float2 f1 = __half22float2(*(__half2*)&u.y);
        r = make_float4(f0.x, f0.y, f1.x, f1.y);
    }
    float4 b = *(const float4*)&bias[lane * 4];
    float o0 = fmaxf(acc.x + r.x + b.x, 0.f);
    float o1 = fmaxf(acc.y + r.y + b.y, 0.f);
    float o2 = fmaxf(acc.z + r.z + b.z, 0.f);
    float o3 = fmaxf(acc.w + r.w + b.w, 0.f);
    __half2* ph = (__half2*)&g_A1[(size_t)n * 128 + lane * 4];
    ph[0] = __halves2half2(__float2half(o0), __float2half(o1));
    ph[1] = __halves2half2(__float2half(o2), __float2half(o3));
}

__global__ void k_agg1(const float* __restrict__ bias, const int* __restrict__ batch) {
    int warp = threadIdx.x >> 5;
    int lane = threadIdx.x & 31;
    int n = blockIdx.x * 8 + warp;
    if (n >= Nn) return;
    int e = g_off[n];
    int end = e + g_cnt[n];
    float4 acc = make_float4(0.f, 0.f, 0.f, 0.f);
    for (; e + 1 < end; e += 2) {
        int s0 = g_src[e], s1 = g_src[e + 1];
        float n0 = g_nrm_s[e], n1 = g_nrm_s[e + 1];
        gather_add(acc, &g_Hi[(size_t)s0 * 128 + lane * 4], n0);
        gather_add(acc, &g_Hi[(size_t)s1 * 128 + lane * 4], n1);
    }
    if (e < end) {
        gather_add(acc, &g_Hi[(size_t)g_src[e] * 128 + lane * 4], g_nrm_s[e]);
    }
    float4 r;
    {
        uint2 u = *(const uint2*)&g_Hr[(size_t)n * 128 + lane * 4];
        float2 f0 = __half22float2(*(__half2*)&u.x);
        float2 f1 = __half22float2(*(__half2*)&u.y);
        r = make_float4(f0.x, f0.y, f1.x, f1.y);
    }
    float4 b = *(const float4*)&bias[lane * 4];
    float4 o;
    o.x = fmaxf(acc.x + r.x + b.x, 0.f);
    o.y = fmaxf(acc.y + r.y + b.y, 0.f);
    o.z = fmaxf(acc.z + r.z + b.z, 0.f);
    o.w = fmaxf(acc.w + r.w + b.w, 0.f);
    int g = batch[n];
    float* p = &g_pool[(size_t)g * 128 + lane * 4];
    atomicAdd(p + 0, o.x);
    atomicAdd(p + 1, o.y);
    atomicAdd(p + 2, o.z);
    atomicAdd(p + 3, o.w);
    if (lane == 0) atomicAdd(&g_pcnt[g], 1.f);
}

// ---------------- pool finalize + MLP ----------------------------------------
__global__ void k_mlp(const float* __restrict__ w1, const float* __restrict__ b1,
                      const float* __restrict__ w2, const float* __restrict__ b2,
                      float* __restrict__ out) {
    __shared__ float gx[128];
    __shared__ float hid[256];
    int g = blockIdx.x;
    int t = threadIdx.x;
    if (t < 128) {
        float c = fmaxf(g_pcnt[g], 1.f);
        gx[t] = g_pool[(size_t)g * 128 + t] / c;
    }
    __syncthreads();
    float acc = b1[t];
    #pragma unroll 8
    for (int k = 0; k < 128; k++) acc += gx[k] * w1[k * 256 + t];
    hid[t] = fmaxf(acc, 0.f);
    __syncthreads();
    int warp = t >> 5, lane = t & 31;
    if (warp < 2) {
        int c = warp;
        float s = 0.f;
        for (int k = lane; k < 256; k += 32) s += hid[k] * w2[k * 2 + c];
        #pragma unroll
        for (int d = 16; d > 0; d >>= 1) s += __shfl_xor_sync(0xFFFFFFFF, s, d);
        if (lane == 0) out[g * 2 + c] = s + b2[c];
    }
}

// ---------------- launch (fork-join: CSR build overlaps split+GEMM0) ----------
extern "C" void kernel_launch(void* const* d_in, const int* in_sizes, int n_in,
                              void* d_out, int out_size) {
    const float* x     = (const float*)d_in[0];
    const int*   ei    = (const int*)d_in[1];
    const float* ea    = (const float*)d_in[2];
    const int*   batch = (const int*)d_in[3];
    const float* w_init0 = (const float*)d_in[4];
    const float* w_root0 = (const float*)d_in[5];
    const float* b0      = (const float*)d_in[6];
    const float* w_init1 = (const float*)d_in[7];
    const float* w_root1 = (const float*)d_in[8];
    const float* b1      = (const float*)d_in[9];
    const float* mlp_w1  = (const float*)d_in[10];
    const float* mlp_b1  = (const float*)d_in[11];
    const float* mlp_w2  = (const float*)d_in[12];
    const float* mlp_b2  = (const float*)d_in[13];
    float* out = (float*)d_out;

    cudaFuncSetAttribute(k_mma<true>,  cudaFuncAttributeMaxDynamicSharedMemorySize, SMEM_BYTES);
    cudaFuncSetAttribute(k_mma<false>, cudaFuncAttributeMaxDynamicSharedMemorySize, SMEM_BYTES);

    const int TB = 256;
    int nBlkE = (Ee + TB - 1) / TB;
    int nz = ((NG * HID > Nn ? NG * HID : Nn) + TB - 1) / TB;
    const int W_TOT = 256 * 256 + 256 * 128;
    dim3 gg((Nn + 127) / 128, 2);

    cudaStream_t s2;
    cudaEvent_t evFork, evJoin;
    bool forked = (cudaStreamCreateWithFlags(&s2, cudaStreamNonBlocking) == cudaSuccess) &&
                  (cudaEventCreateWithFlags(&evFork, cudaEventDisableTiming) == cudaSuccess) &&
                  (cudaEventCreateWithFlags(&evJoin, cudaEventDisableTiming) == cudaSuccess);

    if (forked && cudaEventRecord(evFork, 0) == cudaSuccess &&
        cudaStreamWaitEvent(s2, evFork, 0) == cudaSuccess) {
        // side branch: CSR build
        k_zero<<<nz, TB, 0, s2>>>();
        k_degcnt<<<nBlkE, TB, 0, s2>>>(ei, ea);
        k_scan1<<<NB_SCAN, 1024, 0, s2>>>();
        k_scan3<<<NB_SCAN, 1024, 0, s2>>>();
        k_scatter<<<nBlkE, TB, 0, s2>>>(ei, ea);
        cudaEventRecord(evJoin, s2);

        // main branch: conversions + GEMM0
        k_split_x<<<(Nn * 64 + TB - 1) / TB, TB>>>(x);
        k_wsplit<<<(W_TOT + TB - 1) / TB, TB>>>(w_init0, w_root0, w_init1, w_root1);
        k_mma<true><<<gg, 256, SMEM_BYTES>>>();

        cudaStreamWaitEvent(0, evJoin, 0);
    } else {
        k_zero<<<nz, TB>>>();
        k_degcnt<<<nBlkE, TB>>>(ei, ea);
        k_scan1<<<NB_SCAN, 1024>>>();
        k_scan3<<<NB_SCAN, 1024>>>();
        k_scatter<<<nBlkE, TB>>>(ei, ea);
        k_split_x<<<(Nn * 64 + TB - 1) / TB, TB>>>(x);
        k_wsplit<<<(W_TOT + TB - 1) / TB, TB>>>(w_init0, w_root0, w_init1, w_root1);
        k_mma<true><<<gg, 256, SMEM_BYTES>>>();
    }

    k_agg0<<<(Nn + 7) / 8, 256>>>(b0);
    k_mma<false><<<gg, 256, SMEM_BYTES>>>();
    k_agg1<<<(Nn + 7) / 8, 256>>>(b1, batch);
    k_mlp<<<NG, 256>>>(mlp_w1, mlp_b1, mlp_w2, mlp_b2, out);

    if (forked) {
        cudaStreamDestroy(s2);
        cudaEventDestroy(evFork);
        cudaEventDestroy(evJoin);
    }
}

// round 17
// speedup vs baseline: 1.0455x; 1.0291x over previous
#include <cuda_runtime.h>
#include <cuda_fp16.h>
#include <cstdint>

// Problem constants
#define Nn   100000
#define Ee   1600000
#define HID  128
#define NG   512
#define NB_SCAN 98        // ceil(100000/1024)

// ---------------- scratch (static device memory) -----------------------------
__device__ __align__(128) __half g_Hi[(size_t)Nn * 128];
__device__ __align__(128) __half g_Hr[(size_t)Nn * 128];
__device__ __align__(128) __half g_A1[(size_t)Nn * 128];
__device__ __align__(128) __half g_B0[256 * 256];
__device__ __align__(128) __half g_B1[256 * 128];
__device__ float g_deg[Nn];
__device__ int   g_cnt[Nn];
__device__ int   g_off[Nn];
__device__ int   g_cur[Nn];
__device__ int   g_src[Ee];
__device__ float g_nrm_s[Ee];
__device__ int   g_psum[NB_SCAN];
__device__ float g_pool[NG * HID];
__device__ float g_pcnt[NG];

// ---------------- PTX helpers (base sm_100 features only) --------------------
__device__ __forceinline__ uint32_t s2u(const void* p) {
    uint32_t a;
    asm("{ .reg .u64 t; cvta.to.shared.u64 t, %1; cvt.u32.u64 %0, t; }" : "=r"(a) : "l"(p));
    return a;
}
__device__ __forceinline__ void ldm_x4(uint32_t& r0, uint32_t& r1, uint32_t& r2, uint32_t& r3,
                                       uint32_t addr) {
    asm volatile("ldmatrix.sync.aligned.m8n8.x4.shared.b16 {%0,%1,%2,%3}, [%4];"
                 : "=r"(r0), "=r"(r1), "=r"(r2), "=r"(r3) : "r"(addr));
}
__device__ __forceinline__ void ldm_x2(uint32_t& r0, uint32_t& r1, uint32_t addr) {
    asm volatile("ldmatrix.sync.aligned.m8n8.x2.shared.b16 {%0,%1}, [%2];"
                 : "=r"(r0), "=r"(r1) : "r"(addr));
}
__device__ __forceinline__ void mma_f16(float* c, const uint32_t* a, const uint32_t* b) {
    asm volatile(
        "mma.sync.aligned.m16n8k16.row.col.f32.f16.f16.f32 "
        "{%0,%1,%2,%3}, {%4,%5,%6,%7}, {%8,%9}, {%0,%1,%2,%3};"
        : "+f"(c[0]), "+f"(c[1]), "+f"(c[2]), "+f"(c[3])
        : "r"(a[0]), "r"(a[1]), "r"(a[2]), "r"(a[3]), "r"(b[0]), "r"(b[1]));
}
__device__ __forceinline__ void cpa16(uint32_t saddr, const void* gaddr) {
    asm volatile("cp.async.cg.shared.global [%0], [%1], 16;" :: "r"(saddr), "l"(gaddr));
}
__device__ __forceinline__ void cpa_commit(void) {
    asm volatile("cp.async.commit_group;" ::: "memory");
}
template <int N>
__device__ __forceinline__ void cpa_wait(void) {
    asm volatile("cp.async.wait_group %0;" :: "n"(N) : "memory");
}

// ---------------- fused zero + CSR build kernels ------------------------------
__global__ void k_zero(void) {
    int i = blockIdx.x * blockDim.x + threadIdx.x;
    if (i < Nn) { g_deg[i] = 0.f; g_cnt[i] = 0; }
    if (i < NG * HID) g_pool[i] = 0.f;
    if (i < NG) g_pcnt[i] = 0.f;
}
__global__ void k_degcnt(const int* __restrict__ ei, const float* __restrict__ w) {
    int e = blockIdx.x * blockDim.x + threadIdx.x;
    if (e >= Ee) return;
    int col = ei[Ee + e];
    atomicAdd(&g_deg[col], w[e]);
    atomicAdd(&g_cnt[col], 1);
}
__global__ void k_scan1(void) {
    __shared__ int s[1024];
    int t = threadIdx.x;
    int i = blockIdx.x * 1024 + t;
    if (i < Nn) {
        float d = g_deg[i];
        g_deg[i] = (d > 0.f) ? rsqrtf(d) : 0.f;
    }
    s[t] = (i < Nn) ? g_cnt[i] : 0;
    __syncthreads();
    for (int d = 512; d > 0; d >>= 1) {
        if (t < d) s[t] += s[t + d];
        __syncthreads();
    }
    if (t == 0) g_psum[blockIdx.x] = s[0];
}
// scan3: fused block-base reduction + intra-block scan
__global__ void k_scan3(void) {
    __shared__ int s[1024];
    __shared__ int s_base;
    int t = threadIdx.x;
    int i = blockIdx.x * 1024 + t;
    s[t] = (t < blockIdx.x && t < NB_SCAN) ? g_psum[t] : 0;
    __syncthreads();
    for (int d = 512; d > 0; d >>= 1) {
        if (t < d) s[t] += s[t + d];
        __syncthreads();
    }
    if (t == 0) s_base = s[0];
    __syncthreads();
    int base = s_base;
    int v = (i < Nn) ? g_cnt[i] : 0;
    s[t] = v;
    __syncthreads();
    for (int d = 1; d < 1024; d <<= 1) {
        int add = (t >= d) ? s[t - d] : 0;
        __syncthreads();
        s[t] += add;
        __syncthreads();
    }
    if (i < Nn) {
        int excl = base + s[t] - v;
        g_off[i] = excl;
        g_cur[i] = excl;
    }
}
__global__ void k_scatter(const int* __restrict__ ei, const float* __restrict__ w) {
    int e = blockIdx.x * blockDim.x + threadIdx.x;
    if (e >= Ee) return;
    int row = ei[e];
    int col = ei[Ee + e];
    int pos = atomicAdd(&g_cur[col], 1);
    g_src[pos] = row;
    g_nrm_s[pos] = g_deg[row] * w[e] * g_deg[col];
}

// ---------------- weight conversion (both convs, one launch) ------------------
__global__ void k_wsplit(const float* __restrict__ wi0, const float* __restrict__ wr0,
                         const float* __restrict__ wi1, const float* __restrict__ wr1) {
    int idx = blockIdx.x * blockDim.x + threadIdx.x;
    if (idx < 256 * 256) {
        int n = idx >> 8, k = idx & 255;          // K=256
        float w = (n < 128) ? wi0[k * 128 + n] : wr0[k * 128 + (n - 128)];
        g_B0[idx] = __float2half(w);
    } else if (idx < 256 * 256 + 256 * 128) {
        int j = idx - 256 * 256;
        int n = j >> 7, k = j & 127;              // K=128
        float w = (n < 128) ? wi1[k * 128 + n] : wr1[k * 128 + (n - 128)];
        g_B1[j] = __float2half(w);
    }
}

// ---------------- pipelined mma.sync GEMM ------------------------------------
// FIRST=true: A = x (fp32, K=256) loaded via cp.async into an SMEM fp32 staging
//             buffer, converted to half in-SMEM (fuses the old k_split_x).
// FIRST=false: A = g_A1 (half, K=128) via direct cp.async (as before).
#define SROW 72
#define TILE_HALVES (128 * SROW)
#define SMEM_HALF_BYTES (4 * TILE_HALVES * 2)            // 73728
#define STAGE_FLOATS (128 * 64)                          // fp32 staging tile
#define SMEM_BYTES0 (SMEM_HALF_BYTES + STAGE_FLOATS * 4) // 106496
#define SMEM_BYTES1 SMEM_HALF_BYTES
template <bool FIRST>
__global__ void __launch_bounds__(256, 2) k_mma(const float* __restrict__ xA) {
    constexpr int K  = FIRST ? 256 : 128;
    constexpr int NC = K / 64;
    extern __shared__ __align__(16) __half smem[];
    __half* sA[2] = { smem,                   smem + 2 * TILE_HALVES };
    __half* sB[2] = { smem + TILE_HALVES,     smem + 3 * TILE_HALVES };
    float*  sAf   = (float*)(smem + 4 * TILE_HALVES);    // FIRST only

    const __half* Aw = FIRST ? (const __half*)nullptr : g_A1;
    const __half* Bw = FIRST ? g_B0 : g_B1;

    int tid = threadIdx.x, lane = tid & 31, wid = tid >> 5;
    int warp_m = wid >> 2;
    int warp_n = wid & 3;
    int rowBase = blockIdx.x * 128;
    __half* Hout = (blockIdx.y == 0) ? g_Hi : g_Hr;
    int nBase = blockIdx.y * 128;

    auto issue_chunk = [&](int c, int buf) {
        int k0 = c * 64;
        if constexpr (FIRST) {
            // A: fp32 tile 128x64 -> staging (2048 float4)
            #pragma unroll
            for (int m = tid; m < 2048; m += 256) {
                int row = m >> 4, q = m & 15;
                int rg = rowBase + row;
                if (rg >= Nn) rg = Nn - 1;
                cpa16(s2u(sAf + m * 4), xA + (size_t)rg * 256 + k0 + q * 4);
            }
            // B: half tile 128x64 (1024 x 16B)
            #pragma unroll
            for (int m = tid; m < 1024; m += 256) {
                int row = m >> 3, q = m & 7;
                cpa16(s2u(&sB[buf][row * SROW + q * 8]),
                      &Bw[(size_t)(nBase + row) * K + k0 + q * 8]);
            }
        } else {
            #pragma unroll
            for (int j = tid; j < 2048; j += 256) {
                int isB = j >= 1024;
                int i = j & 1023;
                int row = i >> 3, q = i & 7;
                const __half* src;
                if (!isB) {
                    int rg = rowBase + row;
                    if (rg >= Nn) rg = Nn - 1;
                    src = &Aw[(size_t)rg * K + k0 + q * 8];
                } else {
                    src = &Bw[(size_t)(nBase + row) * K + k0 + q * 8];
                }
                cpa16(s2u(&(isB ? sB : sA)[buf][row * SROW + q * 8]), src);
            }
        }
        cpa_commit();
    };

    float acc[4][4][4] = {};

    issue_chunk(0, 0);
    for (int c = 0; c < NC; ++c) {
        int buf = c & 1;
        cpa_wait<0>();
        __syncthreads();
        if constexpr (FIRST) {
            // convert fp32 staging -> half tile sA[buf]
            #pragma unroll
            for (int j = tid; j < 2048; j += 256) {
                float4 v = ((const float4*)sAf)[j];
                int row = j >> 4, colf = (j & 15) * 4;
                __half2 h0 = __floats2half2_rn(v.x, v.y);
                __half2 h1 = __floats2half2_rn(v.z, v.w);
                uint2 u;
                u.x = *(uint32_t*)&h0;
                u.y = *(uint32_t*)&h1;
                *(uint2*)&sA[buf][row * SROW + colf] = u;
            }
            __syncthreads();   // conversion visible; staging free for next cpa
        }
        if (c + 1 < NC) issue_chunk(c + 1, buf ^ 1);
        uint32_t aB = s2u(sA[buf]), bB = s2u(sB[buf]);
        #pragma unroll
        for (int kk = 0; kk < 4; kk++) {
            int k16 = kk * 16;
            uint32_t a[4][4];
            #pragma unroll
            for (int mt = 0; mt < 4; mt++) {
                int row = warp_m * 64 + mt * 16 + (lane & 15);
                uint32_t addr = aB + (uint32_t)(row * SROW + k16 + (lane >> 4) * 8) * 2;
                ldm_x4(a[mt][0], a[mt][1], a[mt][2], a[mt][3], addr);
            }
            uint32_t b[4][2];
            #pragma unroll
            for (int nt = 0; nt < 4; nt++) {
                int row = warp_n * 32 + nt * 8 + (lane & 7);
                uint32_t addr = bB + (uint32_t)(row * SROW + k16 + ((lane >> 3) & 1) * 8) * 2;
                ldm_x2(b[nt][0], b[nt][1], addr);
            }
            #pragma unroll
            for (int mt = 0; mt < 4; mt++)
                #pragma unroll
                for (int nt = 0; nt < 4; nt++)
                    mma_f16(acc[mt][nt], a[mt], b[nt]);
        }
        __syncthreads();
    }

    #pragma unroll
    for (int mt = 0; mt < 4; mt++) {
        int m0 = rowBase + warp_m * 64 + mt * 16 + (lane >> 2);
        int m1 = m0 + 8;
        #pragma unroll
        for (int nt = 0; nt < 4; nt++) {
            int col = warp_n * 32 + nt * 8 + (lane & 3) * 2;
            if (m0 < Nn) {
                *(__half2*)&Hout[(size_t)m0 * 128 + col] =
                    __halves2half2(__float2half(acc[mt][nt][0]), __float2half(acc[mt][nt][1]));
            }
            if (m1 < Nn) {
                *(__half2*)&Hout[(size_t)m1 * 128 + col] =
                    __halves2half2(__float2half(acc[mt][nt][2]), __float2half(acc[mt][nt][3]));
            }
        }
    }
}

// ---------------- Aggregation: warp per node, fp16 gathers -------------------
__device__ __forceinline__ void gather_add(float4& acc, const __half* rowp, float nm) {
    uint2 u = *(const uint2*)rowp;
    float2 f0 = __half22float2(*(__half2*)&u.x);
    float2 f1 = __half22float2(*(__half2*)&u.y);
    acc.x += nm * f0.x; acc.y += nm * f0.y;
    acc.z += nm * f1.x; acc.w += nm * f1.y;
}

__global__ void k_agg0(const float* __restrict__ bias) {
    int warp = threadIdx.x >> 5;
    int lane = threadIdx.x & 31;
    int n = blockIdx.x * 8 + warp;
    if (n >= Nn) return;
    int e = g_off[n];
    int end = e + g_cnt[n];
    float4 acc = make_float4(0.f, 0.f, 0.f, 0.f);
    for (; e + 1 < end; e += 2) {
        int s0 = g_src[e], s1 = g_src[e + 1];
        float n0 = g_nrm_s[e], n1 = g_nrm_s[e + 1];
        gather_add(acc, &g_Hi[(size_t)s0 * 128 + lane * 4], n0);
        gather_add(acc, &g_Hi[(size_t)s1 * 128 + lane * 4], n1);
    }
    if (e < end) {
        gather_add(acc, &g_Hi[(size_t)g_src[e] * 128 + lane * 4], g_nrm_s[e]);
    }
    float4 r;
    {
        uint2 u = *(const uint2*)&g_Hr[(size_t)n * 128 + lane * 4];
        float2 f0 = __half22float2(*(__half2*)&u.x);
        float2 f1 = __half22float2(*(__half2*)&u.y);
        r = make_float4(f0.x, f0.y, f1.x, f1.y);
    }
    float4 b = *(const float4*)&bias[lane * 4];
    float o0 = fmaxf(acc.x + r.x + b.x, 0.f);
    float o1 = fmaxf(acc.y + r.y + b.y, 0.f);
    float o2 = fmaxf(acc.z + r.z + b.z, 0.f);
    float o3 = fmaxf(acc.w + r.w + b.w, 0.f);
    __half2* ph = (__half2*)&g_A1[(size_t)n * 128 + lane * 4];
    ph[0] = __halves2half2(__float2half(o0), __float2half(o1));
    ph[1] = __halves2half2(__float2half(o2), __float2half(o3));
}

__global__ void k_agg1(const float* __restrict__ bias, const int* __restrict__ batch) {
    int warp = threadIdx.x >> 5;
    int lane = threadIdx.x & 31;
    int n = blockIdx.x * 8 + warp;
    if (n >= Nn) return;
    int e = g_off[n];
    int end = e + g_cnt[n];
    float4 acc = make_float4(0.f, 0.f, 0.f, 0.f);
    for (; e + 1 < end; e += 2) {
        int s0 = g_src[e], s1 = g_src[e + 1];
        float n0 = g_nrm_s[e], n1 = g_nrm_s[e + 1];
        gather_add(acc, &g_Hi[(size_t)s0 * 128 + lane * 4], n0);
        gather_add(acc, &g_Hi[(size_t)s1 * 128 + lane * 4], n1);
    }
    if (e < end) {
        gather_add(acc, &g_Hi[(size_t)g_src[e] * 128 + lane * 4], g_nrm_s[e]);
    }
    float4 r;
    {
        uint2 u = *(const uint2*)&g_Hr[(size_t)n * 128 + lane * 4];
        float2 f0 = __half22float2(*(__half2*)&u.x);
        float2 f1 = __half22float2(*(__half2*)&u.y);
        r = make_float4(f0.x, f0.y, f1.x, f1.y);
    }
    float4 b = *(const float4*)&bias[lane * 4];
    float4 o;
    o.x = fmaxf(acc.x + r.x + b.x, 0.f);
    o.y = fmaxf(acc.y + r.y + b.y, 0.f);
    o.z = fmaxf(acc.z + r.z + b.z, 0.f);
    o.w = fmaxf(acc.w + r.w + b.w, 0.f);
    int g = batch[n];
    float* p = &g_pool[(size_t)g * 128 + lane * 4];
    atomicAdd(p + 0, o.x);
    atomicAdd(p + 1, o.y);
    atomicAdd(p + 2, o.z);
    atomicAdd(p + 3, o.w);
    if (lane == 0) atomicAdd(&g_pcnt[g], 1.f);
}

// ---------------- pool finalize + MLP ----------------------------------------
__global__ void k_mlp(const float* __restrict__ w1, const float* __restrict__ b1,
                      const float* __restrict__ w2, const float* __restrict__ b2,
                      float* __restrict__ out) {
    __shared__ float gx[128];
    __shared__ float hid[256];
    int g = blockIdx.x;
    int t = threadIdx.x;
    if (t < 128) {
        float c = fmaxf(g_pcnt[g], 1.f);
        gx[t] = g_pool[(size_t)g * 128 + t] / c;
    }
    __syncthreads();
    float acc = b1[t];
    #pragma unroll 8
    for (int k = 0; k < 128; k++) acc += gx[k] * w1[k * 256 + t];
    hid[t] = fmaxf(acc, 0.f);
    __syncthreads();
    int warp = t >> 5, lane = t & 31;
    if (warp < 2) {
        int c = warp;
        float s = 0.f;
        for (int k = lane; k < 256; k += 32) s += hid[k] * w2[k * 2 + c];
        #pragma unroll
        for (int d = 16; d > 0; d >>= 1) s += __shfl_xor_sync(0xFFFFFFFF, s, d);
        if (lane == 0) out[g * 2 + c] = s + b2[c];
    }
}

// ---------------- launch (fork-join: CSR build overlaps wsplit+GEMM0) ---------
extern "C" void kernel_launch(void* const* d_in, const int* in_sizes, int n_in,
                              void* d_out, int out_size) {
    const float* x     = (const float*)d_in[0];
    const int*   ei    = (const int*)d_in[1];
    const float* ea    = (const float*)d_in[2];
    const int*   batch = (const int*)d_in[3];
    const float* w_init0 = (const float*)d_in[4];
    const float* w_root0 = (const float*)d_in[5];
    const float* b0      = (const float*)d_in[6];
    const float* w_init1 = (const float*)d_in[7];
    const float* w_root1 = (const float*)d_in[8];
    const float* b1      = (const float*)d_in[9];
    const float* mlp_w1  = (const float*)d_in[10];
    const float* mlp_b1  = (const float*)d_in[11];
    const float* mlp_w2  = (const float*)d_in[12];
    const float* mlp_b2  = (const float*)d_in[13];
    float* out = (float*)d_out;

    cudaFuncSetAttribute(k_mma<true>,  cudaFuncAttributeMaxDynamicSharedMemorySize, SMEM_BYTES0);
    cudaFuncSetAttribute(k_mma<false>, cudaFuncAttributeMaxDynamicSharedMemorySize, SMEM_BYTES1);

    const int TB = 256;
    int nBlkE = (Ee + TB - 1) / TB;
    int nz = ((NG * HID > Nn ? NG * HID : Nn) + TB - 1) / TB;
    const int W_TOT = 256 * 256 + 256 * 128;
    dim3 gg((Nn + 127) / 128, 2);

    cudaStream_t s2;
    cudaEvent_t evFork, evJoin;
    bool forked = (cudaStreamCreateWithFlags(&s2, cudaStreamNonBlocking) == cudaSuccess) &&
                  (cudaEventCreateWithFlags(&evFork, cudaEventDisableTiming) == cudaSuccess) &&
                  (cudaEventCreateWithFlags(&evJoin, cudaEventDisableTiming) == cudaSuccess);

    if (forked && cudaEventRecord(evFork, 0) == cudaSuccess &&
        cudaStreamWaitEvent(s2, evFork, 0) == cudaSuccess) {
        // side branch: CSR build
        k_zero<<<nz, TB, 0, s2>>>();
        k_degcnt<<<nBlkE, TB, 0, s2>>>(ei, ea);
        k_scan1<<<NB_SCAN, 1024, 0, s2>>>();
        k_scan3<<<NB_SCAN, 1024, 0, s2>>>();
        k_scatter<<<nBlkE, TB, 0, s2>>>(ei, ea);
        cudaEventRecord(evJoin, s2);

        // main branch: weight conversion + fused-conversion GEMM0
        k_wsplit<<<(W_TOT + TB - 1) / TB, TB>>>(w_init0, w_root0, w_init1, w_root1);
        k_mma<true><<<gg, 256, SMEM_BYTES0>>>(x);

        cudaStreamWaitEvent(0, evJoin, 0);
    } else {
        k_zero<<<nz, TB>>>();
        k_degcnt<<<nBlkE, TB>>>(ei, ea);
        k_scan1<<<NB_SCAN, 1024>>>();
        k_scan3<<<NB_SCAN, 1024>>>();
        k_scatter<<<nBlkE, TB>>>(ei, ea);
        k_wsplit<<<(W_TOT + TB - 1) / TB, TB>>>(w_init0, w_root0, w_init1, w_root1);
        k_mma<true><<<gg, 256, SMEM_BYTES0>>>(x);
    }

    k_agg0<<<(Nn + 7) / 8, 256>>>(b0);
    k_mma<false><<<gg, 256, SMEM_BYTES1>>>(nullptr);
    k_agg1<<<(Nn + 7) / 8, 256>>>(b1, batch);
    k_mlp<<<NG, 256>>>(mlp_w1, mlp_b1, mlp_w2, mlp_b2, out);

    if (forked) {
        cudaStreamDestroy(s2);
        cudaEventDestroy(evFork);
        cudaEventDestroy(evJoin);
    }
}